// round 5
// baseline (speedup 1.0000x reference)
#include <cuda_runtime.h>
#include <cstdint>
#include <math.h>

// Problem constants (Qwen3MoeSparseMoeBlock: B=2,S=1024 -> T=2048)
#define T_TOK 2048
#define H_DIM 1024
#define I_DIM 512
#define N_EXP 16
#define TOPK  8
#define CAP   2048   // worst-case tokens per expert

// ---------------- scratch (static device globals; no allocation) ----------------
__device__ int   g_counts[N_EXP];
__device__ int   g_rows[N_EXP * CAP];          // permuted row -> token id
__device__ int   g_slot[T_TOK * TOPK];         // (token,k) -> permuted row id
__device__ float g_combine[T_TOK * N_EXP];     // dense combine weights
__device__ float g_hmid[(size_t)N_EXP * CAP * I_DIM];  // 64 MB
__device__ float g_Y   [(size_t)N_EXP * CAP * H_DIM];  // 128 MB

// ---------------- small PTX helpers ----------------
__device__ __forceinline__ uint32_t f2tf32(float f) {
    uint32_t r;
    asm volatile("cvt.rna.tf32.f32 %0, %1;\n" : "=r"(r) : "f"(f));
    return r;
}

__device__ __forceinline__ void mma_tf32(float* d, const uint32_t* a, const uint32_t* b) {
    asm volatile(
        "mma.sync.aligned.m16n8k8.row.col.f32.tf32.tf32.f32 "
        "{%0,%1,%2,%3}, {%4,%5,%6,%7}, {%8,%9}, {%0,%1,%2,%3};\n"
        : "+f"(d[0]), "+f"(d[1]), "+f"(d[2]), "+f"(d[3])
        : "r"(a[0]), "r"(a[1]), "r"(a[2]), "r"(a[3]), "r"(b[0]), "r"(b[1]));
}

__device__ __forceinline__ void cp16(void* smem_dst, const void* gsrc) {
    uint32_t d = (uint32_t)__cvta_generic_to_shared(smem_dst);
    asm volatile("cp.async.ca.shared.global [%0], [%1], 16;\n" :: "r"(d), "l"(gsrc));
}
__device__ __forceinline__ void cp_commit() { asm volatile("cp.async.commit_group;\n"); }
template <int N>
__device__ __forceinline__ void cp_wait() { asm volatile("cp.async.wait_group %0;\n" :: "n"(N)); }

// ---------------- kernel 0: zero counters ----------------
__global__ void init_kernel() {
    if (threadIdx.x < N_EXP) g_counts[threadIdx.x] = 0;
}

// ---------------- kernel 1: router (logits, top-8, routing lists) ----------------
// 8 warps per block, 1 token per warp.
__global__ void __launch_bounds__(256) router_kernel(
    const float* __restrict__ x, const float* __restrict__ gw,
    float* __restrict__ logits_out)
{
    const int warp = threadIdx.x >> 5, lane = threadIdx.x & 31;
    const int t = blockIdx.x * 8 + warp;
    const float* xr = x + (size_t)t * H_DIM;

    float acc[N_EXP];
#pragma unroll
    for (int e = 0; e < N_EXP; e++) acc[e] = 0.f;

    for (int i = 0; i < H_DIM / 32; i++) {
        int h = i * 32 + lane;
        float xv = xr[h];
        const float* g = gw + (size_t)h * N_EXP;
#pragma unroll
        for (int e = 0; e < N_EXP; e++) acc[e] = fmaf(xv, g[e], acc[e]);
    }
#pragma unroll
    for (int e = 0; e < N_EXP; e++) {
#pragma unroll
        for (int off = 16; off; off >>= 1)
            acc[e] += __shfl_xor_sync(0xFFFFFFFFu, acc[e], off);
    }

    if (lane == 0) {
        if (logits_out) {
#pragma unroll
            for (int e = 0; e < N_EXP; e++) logits_out[t * N_EXP + e] = acc[e];
        }
        // top-8 of logits (== top-8 of softmax probs); ties -> lowest index
        float m = acc[0];
#pragma unroll
        for (int e = 1; e < N_EXP; e++) m = fmaxf(m, acc[e]);

        unsigned sel = 0;
        int   idx[TOPK];
        float w[TOPK];
        float ssum = 0.f;
#pragma unroll
        for (int k = 0; k < TOPK; k++) {
            float best = -3.0e38f; int bi = 0;
#pragma unroll
            for (int e = 0; e < N_EXP; e++) {
                if (!((sel >> e) & 1u) && acc[e] > best) { best = acc[e]; bi = e; }
            }
            sel |= (1u << bi);
            idx[k] = bi;
            w[k] = expf(acc[bi] - m);   // softmax denom cancels after renorm
            ssum += w[k];
        }
        float inv = 1.f / ssum;
        float comb[N_EXP];
#pragma unroll
        for (int e = 0; e < N_EXP; e++) comb[e] = 0.f;
#pragma unroll
        for (int k = 0; k < TOPK; k++) comb[idx[k]] = w[k] * inv;
#pragma unroll
        for (int e = 0; e < N_EXP; e++) g_combine[t * N_EXP + e] = comb[e];

#pragma unroll
        for (int k = 0; k < TOPK; k++) {
            int e = idx[k];
            int pos = atomicAdd(&g_counts[e], 1);
            g_rows[e * CAP + pos] = t;
            g_slot[t * TOPK + k] = e * CAP + pos;
        }
    }
}

// ---------------- GEMM tiling config ----------------
#define BM 128
#define BN 64
#define BK 16
#define AST 20   // A smem row stride (floats): 16B aligned, conflict-free frag reads
#define BST 72   // B smem row stride (floats): 16B aligned, conflict-free frag reads

// ---------------- kernel 2: fused gate+up grouped GEMM + SiLU epilogue ----------------
// grid: (I/BN=8, CAP/BM=16, E=16), block 256 (8 warps in 4x2, warp tile 32x32).
__global__ void __launch_bounds__(256, 2) gu_kernel(
    const float* __restrict__ x,
    const float* __restrict__ wg_all,
    const float* __restrict__ wu_all)
{
    const int e = blockIdx.z;
    const int n_e = g_counts[e];
    const int m0 = blockIdx.y * BM;
    if (m0 >= n_e) return;
    const int n0 = blockIdx.x * BN;
    const float* wg = wg_all + (size_t)e * H_DIM * I_DIM;
    const float* wu = wu_all + (size_t)e * H_DIM * I_DIM;

    __shared__ float As[2][BM * AST];
    __shared__ float Bg[2][BK * BST];
    __shared__ float Bu[2][BK * BST];
    __shared__ int   rtok[BM];
    __shared__ float rw[BM];

    const int tid = threadIdx.x;
    if (tid < BM) {
        int r = m0 + tid;
        int tok = 0; float w = 0.f;
        if (r < n_e) { tok = g_rows[e * CAP + r]; w = g_combine[tok * N_EXP + e]; }
        rtok[tid] = tok; rw[tid] = w;
    }
    __syncthreads();

    const int warp = tid >> 5, lane = tid & 31;
    const int gid = lane >> 2, tig = lane & 3;
    const int wm = (warp >> 1) * 32, wn = (warp & 1) * 32;

    float dG[2][4][4] = {}, dU[2][4][4] = {};

    auto load_stage = [&](int kt, int buf) {
        const int k0 = kt * BK;
#pragma unroll
        for (int j = 0; j < 2; j++) {
            int idx = tid + 256 * j;              // 512 float4 = 128 rows x 4
            int row = idx >> 2, c4 = idx & 3;
            cp16(&As[buf][row * AST + c4 * 4],
                 x + (size_t)rtok[row] * H_DIM + k0 + c4 * 4);
        }
        {
            int row = tid >> 4, c4 = tid & 15;    // 256 float4 = 16 rows x 16
            cp16(&Bg[buf][row * BST + c4 * 4],
                 wg + (size_t)(k0 + row) * I_DIM + n0 + c4 * 4);
            cp16(&Bu[buf][row * BST + c4 * 4],
                 wu + (size_t)(k0 + row) * I_DIM + n0 + c4 * 4);
        }
        cp_commit();
    };

    const int KT = H_DIM / BK;  // 64
    load_stage(0, 0);

    for (int kt = 0; kt < KT; kt++) {
        int buf = kt & 1;
        if (kt + 1 < KT) { load_stage(kt + 1, buf ^ 1); cp_wait<1>(); }
        else             { cp_wait<0>(); }
        __syncthreads();

        const float* As_ = As[buf];
        const float* Bg_ = Bg[buf];
        const float* Bu_ = Bu[buf];
#pragma unroll
        for (int ks = 0; ks < 2; ks++) {
            uint32_t a[2][4];
#pragma unroll
            for (int mi = 0; mi < 2; mi++) {
                int r0 = wm + mi * 16;
                int c0 = ks * 8;
                a[mi][0] = f2tf32(As_[(r0 + gid)     * AST + c0 + tig]);
                a[mi][1] = f2tf32(As_[(r0 + gid + 8) * AST + c0 + tig]);
                a[mi][2] = f2tf32(As_[(r0 + gid)     * AST + c0 + tig + 4]);
                a[mi][3] = f2tf32(As_[(r0 + gid + 8) * AST + c0 + tig + 4]);
            }
#pragma unroll
            for (int ni = 0; ni < 4; ni++) {
                int c = wn + ni * 8 + gid;
                uint32_t bg[2], bu[2];
                bg[0] = f2tf32(Bg_[(ks * 8 + tig)     * BST + c]);
                bg[1] = f2tf32(Bg_[(ks * 8 + tig + 4) * BST + c]);
                bu[0] = f2tf32(Bu_[(ks * 8 + tig)     * BST + c]);
                bu[1] = f2tf32(Bu_[(ks * 8 + tig + 4) * BST + c]);
#pragma unroll
                for (int mi = 0; mi < 2; mi++) {
                    mma_tf32(dG[mi][ni], a[mi], bg);
                    mma_tf32(dU[mi][ni], a[mi], bu);
                }
            }
        }
        __syncthreads();
    }

    // epilogue: hmid = silu(G) * U * combine_weight
#pragma unroll
    for (int mi = 0; mi < 2; mi++) {
#pragma unroll
        for (int ni = 0; ni < 4; ni++) {
            int rr = wm + mi * 16 + gid;
            int cc = wn + ni * 8 + tig * 2;
#pragma unroll
            for (int q = 0; q < 4; q++) {
                int r = rr + (q >> 1) * 8;
                int c = cc + (q & 1);
                if (m0 + r < n_e) {
                    float g = dG[mi][ni][q], u = dU[mi][ni][q];
                    float s = g / (1.f + expf(-g));
                    g_hmid[(size_t)(e * CAP + m0 + r) * I_DIM + n0 + c] = s * u * rw[r];
                }
            }
        }
    }
}

// ---------------- kernel 3: down grouped GEMM ----------------
// grid: (H/BN=16, CAP/BM=16, E=16), block 256.
__global__ void __launch_bounds__(256, 2) down_kernel(const float* __restrict__ wd_all)
{
    const int e = blockIdx.z;
    const int n_e = g_counts[e];
    const int m0 = blockIdx.y * BM;
    if (m0 >= n_e) return;
    const int n0 = blockIdx.x * BN;
    const float* wd  = wd_all + (size_t)e * I_DIM * H_DIM;
    const float* Ain = g_hmid + (size_t)e * CAP * I_DIM;

    __shared__ float As[2][BM * AST];
    __shared__ float Bs[2][BK * BST];

    const int tid = threadIdx.x;
    const int warp = tid >> 5, lane = tid & 31;
    const int gid = lane >> 2, tig = lane & 3;
    const int wm = (warp >> 1) * 32, wn = (warp & 1) * 32;

    float dD[2][4][4] = {};

    auto load_stage = [&](int kt, int buf) {
        const int k0 = kt * BK;
#pragma unroll
        for (int j = 0; j < 2; j++) {
            int idx = tid + 256 * j;
            int row = idx >> 2, c4 = idx & 3;
            cp16(&As[buf][row * AST + c4 * 4],
                 Ain + (size_t)(m0 + row) * I_DIM + k0 + c4 * 4);
        }
        {
            int row = tid >> 4, c4 = tid & 15;
            cp16(&Bs[buf][row * BST + c4 * 4],
                 wd + (size_t)(k0 + row) * H_DIM + n0 + c4 * 4);
        }
        cp_commit();
    };

    const int KT = I_DIM / BK;  // 32
    load_stage(0, 0);

    for (int kt = 0; kt < KT; kt++) {
        int buf = kt & 1;
        if (kt + 1 < KT) { load_stage(kt + 1, buf ^ 1); cp_wait<1>(); }
        else             { cp_wait<0>(); }
        __syncthreads();

        const float* As_ = As[buf];
        const float* Bs_ = Bs[buf];
#pragma unroll
        for (int ks = 0; ks < 2; ks++) {
            uint32_t a[2][4];
#pragma unroll
            for (int mi = 0; mi < 2; mi++) {
                int r0 = wm + mi * 16;
                int c0 = ks * 8;
                a[mi][0] = f2tf32(As_[(r0 + gid)     * AST + c0 + tig]);
                a[mi][1] = f2tf32(As_[(r0 + gid + 8) * AST + c0 + tig]);
                a[mi][2] = f2tf32(As_[(r0 + gid)     * AST + c0 + tig + 4]);
                a[mi][3] = f2tf32(As_[(r0 + gid + 8) * AST + c0 + tig + 4]);
            }
#pragma unroll
            for (int ni = 0; ni < 4; ni++) {
                int c = wn + ni * 8 + gid;
                uint32_t b[2];
                b[0] = f2tf32(Bs_[(ks * 8 + tig)     * BST + c]);
                b[1] = f2tf32(Bs_[(ks * 8 + tig + 4) * BST + c]);
#pragma unroll
                for (int mi = 0; mi < 2; mi++) mma_tf32(dD[mi][ni], a[mi], b);
            }
        }
        __syncthreads();
    }

#pragma unroll
    for (int mi = 0; mi < 2; mi++) {
#pragma unroll
        for (int ni = 0; ni < 4; ni++) {
            int rr = wm + mi * 16 + gid;
            int cc = wn + ni * 8 + tig * 2;
#pragma unroll
            for (int q = 0; q < 4; q++) {
                int r = rr + (q >> 1) * 8;
                int c = cc + (q & 1);
                if (m0 + r < n_e)
                    g_Y[(size_t)(e * CAP + m0 + r) * H_DIM + n0 + c] = dD[mi][ni][q];
            }
        }
    }
}

// ---------------- kernel 4: per-token combine (gather 8 weighted rows) ----------------
__global__ void __launch_bounds__(256) combine_kernel(float* __restrict__ out)
{
    const int t = blockIdx.x;
    __shared__ int slots[TOPK];
    if (threadIdx.x < TOPK) slots[threadIdx.x] = g_slot[t * TOPK + threadIdx.x];
    __syncthreads();

    int h4 = threadIdx.x;  // 256 float4 per token (H=1024)
    float4 acc = make_float4(0.f, 0.f, 0.f, 0.f);
#pragma unroll
    for (int k = 0; k < TOPK; k++) {
        const float4* y = (const float4*)(g_Y + (size_t)slots[k] * H_DIM);
        float4 v = y[h4];
        acc.x += v.x; acc.y += v.y; acc.z += v.z; acc.w += v.w;
    }
    ((float4*)out)[(size_t)t * (H_DIM / 4) + h4] = acc;
}

// ---------------- launch ----------------
extern "C" void kernel_launch(void* const* d_in, const int* in_sizes, int n_in,
                              void* d_out, int out_size)
{
    const float* x      = (const float*)d_in[0];  // [2,1024,1024]
    const float* gate_w = (const float*)d_in[1];  // [1024,16]
    const float* w_gate = (const float*)d_in[2];  // [16,1024,512]
    const float* w_up   = (const float*)d_in[3];  // [16,1024,512]
    const float* w_down = (const float*)d_in[4];  // [16,512,1024]
    float* out = (float*)d_out;

    float* logits = nullptr;
    if (out_size >= T_TOK * H_DIM + T_TOK * N_EXP)
        logits = out + (size_t)T_TOK * H_DIM;

    init_kernel<<<1, 32>>>();
    router_kernel<<<T_TOK / 8, 256>>>(x, gate_w, logits);
    gu_kernel<<<dim3(I_DIM / BN, CAP / BM, N_EXP), 256>>>(x, w_gate, w_up);
    down_kernel<<<dim3(H_DIM / BN, CAP / BM, N_EXP), 256>>>(w_down);
    combine_kernel<<<T_TOK, 256>>>(out);
}